// round 15
// baseline (speedup 1.0000x reference)
#include <cuda_runtime.h>
#include <cuda_bf16.h>
#include <cstdint>

#define BDIM 4
#define TDIM 2048
#define CDIM 1024
#define WIN  16

typedef __nv_bfloat16  bf16;
typedef __nv_bfloat162 bf162;

// ---------------- scratch (allocation-free rule: __device__ globals) --------
#define NTC ((size_t)BDIM * TDIM * CDIM)
#define NTT ((size_t)BDIM * TDIM * TDIM)
#define NCC ((size_t)CDIM * CDIM)
__device__ bf16  g_xh[NTC],  g_xl[NTC];
__device__ bf16  g_wqh[NCC], g_wql[NCC], g_wkh[NCC], g_wkl[NCC];
__device__ bf16  g_wvh[NCC], g_wvl[NCC], g_woh[NCC], g_wol[NCC];
__device__ bf16  g_qh[NTC],  g_ql[NTC],  g_kh[NTC],  g_kl[NTC];
__device__ float g_v[NTC];
__device__ bf16  g_vth[NTC], g_vtl[NTC];          // [b][c][t]
__device__ bf16  g_ph[NTT],  g_pl[NTT];           // unnormalized exp scores
__device__ float g_rsum[(size_t)BDIM * TDIM];     // row sums of exp
__device__ bf16  g_yh[NTC],  g_yl[NTC];

// ---------------- low-level helpers (sm_80/90-portable PTX only) ------------
__device__ __forceinline__ uint32_t smem_u32(const void* p) {
    uint32_t a;
    asm("{ .reg .u64 t; cvta.to.shared.u64 t, %1; cvt.u32.u64 %0, t; }"
        : "=r"(a) : "l"(p));
    return a;
}
__device__ __forceinline__ uint32_t swz(uint32_t off) {      // SW128 swizzle
    return off ^ ((off >> 3) & 0x70);
}
__device__ __forceinline__ void cp16(uint32_t dst, const void* src) {
    asm volatile("cp.async.cg.shared.global [%0], [%1], 16;"
                 :: "r"(dst), "l"(src));
}
// .noinc: completion-arrive counts against the barrier's init count (the
// default form would +1 the pending count first -> net zero -> deadlock).
__device__ __forceinline__ void cp_async_mbar_arrive(uint32_t mbar) {
    asm volatile("cp.async.mbarrier.arrive.noinc.shared.b64 [%0];"
                 :: "r"(mbar) : "memory");
}
__device__ __forceinline__ void mbar_init(uint32_t mbar, uint32_t cnt) {
    asm volatile("mbarrier.init.shared.b64 [%0], %1;"
                 :: "r"(mbar), "r"(cnt) : "memory");
}
__device__ __forceinline__ void mbar_arrive(uint32_t mbar) {
    asm volatile("mbarrier.arrive.shared.b64 _, [%0];"
                 :: "r"(mbar) : "memory");
}
__device__ __forceinline__ void mbar_wait(uint32_t mbar, uint32_t parity) {
    asm volatile(
        "{\n\t.reg .pred P;\n\t"
        "WL%=:\n\t"
        "mbarrier.try_wait.parity.acquire.cta.shared::cta.b64 P, [%0], %1;\n\t"
        "@!P bra WL%=;\n\t}"
        :: "r"(mbar), "r"(parity) : "memory");
}
__device__ __forceinline__ void ldsm4(uint32_t (&r)[4], uint32_t addr) {
    asm volatile("ldmatrix.sync.aligned.m8n8.x4.shared.b16 {%0,%1,%2,%3}, [%4];"
                 : "=r"(r[0]), "=r"(r[1]), "=r"(r[2]), "=r"(r[3]) : "r"(addr));
}
__device__ __forceinline__ void mma16816(float (&c)[4], const uint32_t (&a)[4],
                                         const uint32_t (&b)[2]) {
    asm volatile(
        "mma.sync.aligned.m16n8k16.row.col.f32.bf16.bf16.f32 "
        "{%0,%1,%2,%3}, {%4,%5,%6,%7}, {%8,%9}, {%0,%1,%2,%3};"
        : "+f"(c[0]), "+f"(c[1]), "+f"(c[2]), "+f"(c[3])
        : "r"(a[0]), "r"(a[1]), "r"(a[2]), "r"(a[3]), "r"(b[0]), "r"(b[1]));
}
__device__ __forceinline__ void split1(float v, bf16& h, bf16& l) {
    h = __float2bfloat16_rn(v);
    l = __float2bfloat16_rn(v - __bfloat162float(h));
}
__device__ __forceinline__ void split_store2(bf16* H, bf16* L, size_t idx,
                                             float v0, float v1) {
    bf16 h0, l0, h1, l1;
    split1(v0, h0, l0);
    split1(v1, h1, l1);
    *reinterpret_cast<bf162*>(&H[idx]) = bf162(h0, h1);
    *reinterpret_cast<bf162*>(&L[idx]) = bf162(l0, l1);
}

// ===========================================================================
// Warp-specialized 128x128 mainloop: 8 consumer warps (4x2, 32x64 tiles) +
// 1 producer warp. 3-stage ring with per-stage full/empty mbarriers. No
// __syncthreads in the mainloop -> consumer warps skew, spreading LDSM bursts.
// full[s]: count 32 (producer lanes via cp.async.mbarrier.arrive.noinc).
// empty[s]: count 8 (consumer warps, lane0). Phase 0 pre-completed at init.
// ===========================================================================
#define NCW         8
#define NTHREADS    288            // 8 consumer warps + 1 producer warp
#define STAGE_BYTES 65536
#define NSTAGE      3
#define SMEM_SZ     (1024 + NSTAGE * STAGE_BYTES)

struct Frag {
    uint32_t ah[2][4], al[2][4];
    uint32_t bh[8][2], bl[8][2];
};

__device__ __forceinline__ void frag_load(Frag& f, uint32_t tAh, uint32_t tAl,
                                          uint32_t tBh, uint32_t tBl,
                                          uint32_t aoff, uint32_t boff, int kk)
{
    const uint32_t ka = (uint32_t)kk * 32;           // 16 bf16 = 32 bytes
    #pragma unroll
    for (int mi = 0; mi < 2; mi++) {
        const uint32_t off = aoff + mi * 2048 + ka;
        ldsm4(f.ah[mi], tAh + swz(off));
        ldsm4(f.al[mi], tAl + swz(off));
    }
    #pragma unroll
    for (int p = 0; p < 4; p++) {                    // each ldsm4 covers 2 n-tiles
        const uint32_t off = boff + (uint32_t)(p * 16 * 128) + ka;
        uint32_t t4[4];
        ldsm4(t4, tBh + swz(off));
        f.bh[p * 2][0] = t4[0]; f.bh[p * 2][1] = t4[1];
        f.bh[p * 2 + 1][0] = t4[2]; f.bh[p * 2 + 1][1] = t4[3];
        ldsm4(t4, tBl + swz(off));
        f.bl[p * 2][0] = t4[0]; f.bl[p * 2][1] = t4[1];
        f.bl[p * 2 + 1][0] = t4[2]; f.bl[p * 2 + 1][1] = t4[3];
    }
}

__device__ __forceinline__ void frag_mma(float acc[2][8][4], const Frag& f)
{
    #pragma unroll
    for (int mi = 0; mi < 2; mi++)
        #pragma unroll
        for (int ni = 0; ni < 8; ni++)
            mma16816(acc[mi][ni], f.ah[mi], f.bh[ni]);
    #pragma unroll
    for (int mi = 0; mi < 2; mi++)
        #pragma unroll
        for (int ni = 0; ni < 8; ni++)
            mma16816(acc[mi][ni], f.ah[mi], f.bl[ni]);
    #pragma unroll
    for (int mi = 0; mi < 2; mi++)
        #pragma unroll
        for (int ni = 0; ni < 8; ni++)
            mma16816(acc[mi][ni], f.al[mi], f.bh[ni]);
}

// mbarrier ring at sbase: [full0, empty0, full1, empty1, full2, empty2]
__device__ __forceinline__ uint32_t full_bar(uint32_t sbase, int s)  { return sbase + s * 16; }
__device__ __forceinline__ uint32_t empty_bar(uint32_t sbase, int s) { return sbase + s * 16 + 8; }

// Shared init: thread 0 inits barriers + pre-completes empty phase 0.
// Caller must __syncthreads() after.
__device__ __forceinline__ void ws_init(uint32_t sbase, int tid)
{
    if (tid == 0) {
        #pragma unroll
        for (int s = 0; s < NSTAGE; s++) {
            mbar_init(full_bar(sbase, s), 32);
            mbar_init(empty_bar(sbase, s), NCW);
            #pragma unroll
            for (int i = 0; i < NCW; i++) mbar_arrive(empty_bar(sbase, s));
        }
    }
}

// Producer warp body: fills stages, signals full via cp.async completion.
__device__ __forceinline__ void producer_loop(
    const bf16* __restrict__ Ah, const bf16* __restrict__ Al,
    const bf16* __restrict__ Bh, const bf16* __restrict__ Bl,
    int K_, int kstart, int m0, int n0, int lane, uint32_t sbase)
{
    const int nch = (K_ - kstart) >> 6;
    const uint32_t stages = sbase + 1024;
    int stage = 0, phase = 0;
    for (int ci = 0; ci < nch; ci++) {
        mbar_wait(empty_bar(sbase, stage), phase);
        const int k0 = kstart + (ci << 6);
        const uint32_t sb = stages + stage * STAGE_BYTES;
        #pragma unroll 8
        for (int i = 0; i < 32; i++) {               // 1024 lines/tile, 32/lane
            const int id = lane + i * 32;
            const int row = id >> 3, kc = id & 7;
            const uint32_t d = swz((uint32_t)(row * 128 + kc * 16));
            const size_t ga = (size_t)(m0 + row) * K_ + k0 + kc * 8;
            const size_t gb = (size_t)(n0 + row) * K_ + k0 + kc * 8;
            cp16(sb +         d, Ah + ga);
            cp16(sb + 16384 + d, Al + ga);
            cp16(sb + 32768 + d, Bh + gb);
            cp16(sb + 49152 + d, Bl + gb);
        }
        cp_async_mbar_arrive(full_bar(sbase, stage));
        if (++stage == NSTAGE) { stage = 0; phase ^= 1; }
    }
}

// Consumer warp body: waits full, runs frag-pipelined mma, arrives empty.
__device__ __forceinline__ void consumer_loop(
    int K_, int kstart, int wid, int lane, uint32_t sbase, float acc[2][8][4])
{
    const int nch = (K_ - kstart) >> 6;
    const uint32_t stages = sbase + 1024;
    const int warpM = wid & 3, warpN = wid >> 2;
    const uint32_t aoff = (uint32_t)((warpM * 32 + (lane & 15)) * 128 + (lane >> 4) * 16);
    const int bgrp = lane >> 3, bl8 = lane & 7;
    const uint32_t boff = (uint32_t)((warpN * 64 + (bgrp >> 1) * 8 + bl8) * 128 + (bgrp & 1) * 16);

    Frag f0, f1;
    int stage = 0, phase = 0;
    for (int ci = 0; ci < nch; ci++) {
        mbar_wait(full_bar(sbase, stage), phase);
        const uint32_t tb  = stages + stage * STAGE_BYTES;
        const uint32_t tAh = tb, tAl = tb + 16384, tBh = tb + 32768, tBl = tb + 49152;

        frag_load(f0, tAh, tAl, tBh, tBl, aoff, boff, 0);
        frag_load(f1, tAh, tAl, tBh, tBl, aoff, boff, 1);
        frag_mma(acc, f0);
        frag_load(f0, tAh, tAl, tBh, tBl, aoff, boff, 2);
        frag_mma(acc, f1);
        frag_load(f1, tAh, tAl, tBh, tBl, aoff, boff, 3);
        frag_mma(acc, f0);
        frag_mma(acc, f1);

        __syncwarp();
        if (lane == 0) mbar_arrive(empty_bar(sbase, stage));
        if (++stage == NSTAGE) { stage = 0; phase ^= 1; }
    }
}

// ===========================================================================
// Merged Q/K/V projections: z=0 -> Q (hi/lo), z=1 -> K (hi/lo), z=2 -> V fp32.
// ===========================================================================
__global__ void __launch_bounds__(NTHREADS)
qkv_pipe(const bf16* __restrict__ Ah, const bf16* __restrict__ Al,
         const bf16* __restrict__ BhQ, const bf16* __restrict__ BlQ,
         const float* __restrict__ bQ, bf16* __restrict__ ChQ, bf16* __restrict__ ClQ,
         const bf16* __restrict__ BhK, const bf16* __restrict__ BlK,
         const float* __restrict__ bK, bf16* __restrict__ ChK, bf16* __restrict__ ClK,
         const bf16* __restrict__ BhV, const bf16* __restrict__ BlV,
         const float* __restrict__ bV, float* __restrict__ CfV)
{
    extern __shared__ __align__(1024) char smem[];
    const int z = blockIdx.z;
    const bf16 *Bh, *Bl;
    const float* bias;
    bf16 *Ch = nullptr, *Cl = nullptr;
    float* Cf = nullptr;
    if (z == 0)      { Bh = BhQ; Bl = BlQ; bias = bQ; Ch = ChQ; Cl = ClQ; }
    else if (z == 1) { Bh = BhK; Bl = BlK; bias = bK; Ch = ChK; Cl = ClK; }
    else             { Bh = BhV; Bl = BlV; bias = bV; Cf = CfV; }

    const int m0 = blockIdx.y * 128;
    const int n0 = blockIdx.x * 128;
    const int tid = threadIdx.x, wid = tid >> 5, lane = tid & 31;
    const uint32_t sbase = smem_u32(smem);

    ws_init(sbase, tid);
    __syncthreads();

    if (wid == NCW) {
        producer_loop(Ah, Al, Bh, Bl, CDIM, 0, m0, n0, lane, sbase);
        return;
    }

    float acc[2][8][4];
    #pragma unroll
    for (int i = 0; i < 2; i++)
        #pragma unroll
        for (int j = 0; j < 8; j++)
            #pragma unroll
            for (int t = 0; t < 4; t++) acc[i][j][t] = 0.0f;

    consumer_loop(CDIM, 0, wid, lane, sbase, acc);

    const int warpM = wid & 3, warpN = wid >> 2;
    const int rbase = m0 + warpM * 32 + (lane >> 2);
    const int cbase = n0 + warpN * 64 + (lane & 3) * 2;
    #pragma unroll
    for (int mi = 0; mi < 2; mi++) {
        const int ra = rbase + mi * 16, rb = ra + 8;
        #pragma unroll
        for (int ni = 0; ni < 8; ni++) {
            const int c = cbase + ni * 8;
            const float b0 = bias[c], b1 = bias[c + 1];
            const float v0 = acc[mi][ni][0] + b0, v1 = acc[mi][ni][1] + b1;
            const float v2 = acc[mi][ni][2] + b0, v3 = acc[mi][ni][3] + b1;
            if (Cf) {
                *reinterpret_cast<float2*>(&Cf[(size_t)ra * CDIM + c]) = make_float2(v0, v1);
                *reinterpret_cast<float2*>(&Cf[(size_t)rb * CDIM + c]) = make_float2(v2, v3);
            } else {
                split_store2(Ch, Cl, (size_t)ra * CDIM + c, v0, v1);
                split_store2(Ch, Cl, (size_t)rb * CDIM + c, v2, v3);
            }
        }
    }
}

// ===========================================================================
// gemm_pipe<EPI, AVSKIP>: EPI 0 fp32+bias (O proj); EPI 1 scores (exp+mask+
// rowsum atomics, masked tiles exit without writing); EPI 3 AV (normalize).
// AVSKIP: start K at m0-64 (P exactly 0 below the band).
// ===========================================================================
template <int EPI, bool AVSKIP>
__global__ void __launch_bounds__(NTHREADS)
gemm_pipe(const bf16* __restrict__ Ah, const bf16* __restrict__ Al,
          const bf16* __restrict__ Bh, const bf16* __restrict__ Bl,
          const float* __restrict__ bias, float* __restrict__ rowsum,
          float* __restrict__ Cf, bf16* __restrict__ Ch, bf16* __restrict__ Cl,
          int N_, int K_, size_t sA, size_t sB, size_t sC, float scale)
{
    extern __shared__ __align__(1024) char smem[];
    const int bz = blockIdx.z;
    Ah += (size_t)bz * sA;  Al += (size_t)bz * sA;
    Bh += (size_t)bz * sB;  Bl += (size_t)bz * sB;
    const size_t cOff = (size_t)bz * sC;

    const int m0 = blockIdx.y * 128;
    const int n0 = blockIdx.x * 128;
    const int tid = threadIdx.x, wid = tid >> 5, lane = tid & 31;

    if (EPI == 1) {
        if (n0 + 127 < m0 - WIN) return;     // fully masked tile
    }

    int kstart = 0;
    if (AVSKIP) kstart = (m0 >= 64) ? m0 - 64 : 0;

    const uint32_t sbase = smem_u32(smem);
    ws_init(sbase, tid);
    __syncthreads();

    if (wid == NCW) {
        producer_loop(Ah, Al, Bh, Bl, K_, kstart, m0, n0, lane, sbase);
        return;
    }

    float acc[2][8][4];
    #pragma unroll
    for (int i = 0; i < 2; i++)
        #pragma unroll
        for (int j = 0; j < 8; j++)
            #pragma unroll
            for (int t = 0; t < 4; t++) acc[i][j][t] = 0.0f;

    consumer_loop(K_, kstart, wid, lane, sbase, acc);

    const int warpM = wid & 3, warpN = wid >> 2;
    const int rbase = m0 + warpM * 32 + (lane >> 2);
    const int cbase = n0 + warpN * 64 + (lane & 3) * 2;
    #pragma unroll
    for (int mi = 0; mi < 2; mi++) {
        const int ra = rbase + mi * 16, rb = ra + 8;
        float sum_a = 0.f, sum_b = 0.f;
        float ia = 0.f, ib = 0.f;
        if (EPI == 3) {
            ia = 1.0f / __ldg(&rowsum[bz * TDIM + ra]);
            ib = 1.0f / __ldg(&rowsum[bz * TDIM + rb]);
        }
        #pragma unroll
        for (int ni = 0; ni < 8; ni++) {
            const int c = cbase + ni * 8;
            const float v0 = acc[mi][ni][0], v1 = acc[mi][ni][1];
            const float v2 = acc[mi][ni][2], v3 = acc[mi][ni][3];
            if (EPI == 0) {
                const float b0 = bias[c], b1 = bias[c + 1];
                *reinterpret_cast<float2*>(&Cf[cOff + (size_t)ra * N_ + c]) =
                    make_float2(v0 + b0, v1 + b1);
                *reinterpret_cast<float2*>(&Cf[cOff + (size_t)rb * N_ + c]) =
                    make_float2(v2 + b0, v3 + b1);
            } else if (EPI == 1) {
                const float p0 = (c     >= ra - WIN) ? __expf(v0 * scale) : 0.f;
                const float p1 = (c + 1 >= ra - WIN) ? __expf(v1 * scale) : 0.f;
                const float p2 = (c     >= rb - WIN) ? __expf(v2 * scale) : 0.f;
                const float p3 = (c + 1 >= rb - WIN) ? __expf(v3 * scale) : 0.f;
                split_store2(Ch, Cl, cOff + (size_t)ra * N_ + c, p0, p1);
                split_store2(Ch, Cl, cOff + (size_t)rb * N_ + c, p2, p3);
                sum_a += p0 + p1;
                sum_b += p2 + p3;
            } else {  // EPI == 3
                split_store2(Ch, Cl, cOff + (size_t)ra * N_ + c, v0 * ia, v1 * ia);
                split_store2(Ch, Cl, cOff + (size_t)rb * N_ + c, v2 * ib, v3 * ib);
            }
        }
        if (EPI == 1) {
            sum_a += __shfl_xor_sync(0xffffffffu, sum_a, 1);
            sum_a += __shfl_xor_sync(0xffffffffu, sum_a, 2);
            sum_b += __shfl_xor_sync(0xffffffffu, sum_b, 1);
            sum_b += __shfl_xor_sync(0xffffffffu, sum_b, 2);
            if ((lane & 3) == 0) {
                atomicAdd(&rowsum[bz * TDIM + ra], sum_a);
                atomicAdd(&rowsum[bz * TDIM + rb], sum_b);
            }
        }
    }
}

// ---------------------------------------------------------------------------
__global__ void __launch_bounds__(256)
zero_rowsum(float* __restrict__ r)
{
    r[blockIdx.x * 256 + threadIdx.x] = 0.0f;
}

// ---------------------------------------------------------------------------
// One-shot fp32 -> bf16 hi/lo split of x + all four weights (float4 units)
// ---------------------------------------------------------------------------
__global__ void __launch_bounds__(256)
split_all(const float* __restrict__ x,  const float* __restrict__ Wq,
          const float* __restrict__ Wk, const float* __restrict__ Wv,
          const float* __restrict__ Wo,
          bf16* __restrict__ xh,  bf16* __restrict__ xl,
          bf16* __restrict__ qh,  bf16* __restrict__ ql,
          bf16* __restrict__ kh,  bf16* __restrict__ kl,
          bf16* __restrict__ vh,  bf16* __restrict__ vl,
          bf16* __restrict__ oh,  bf16* __restrict__ ol)
{
    const size_t nX = NTC / 4, nW = NCC / 4;
    size_t i = (size_t)blockIdx.x * 256 + threadIdx.x;
    const float* src;
    bf16 *H, *L;
    size_t j;
    if (i < nX)               { src = x;  H = xh; L = xl; j = i; }
    else if (i < nX + nW)     { src = Wq; H = qh; L = ql; j = i - nX; }
    else if (i < nX + 2 * nW) { src = Wk; H = kh; L = kl; j = i - nX - nW; }
    else if (i < nX + 3 * nW) { src = Wv; H = vh; L = vl; j = i - nX - 2 * nW; }
    else                      { src = Wo; H = oh; L = ol; j = i - nX - 3 * nW; }
    const float4 v = reinterpret_cast<const float4*>(src)[j];
    bf16 h0, l0, h1, l1, h2, l2, h3, l3;
    split1(v.x, h0, l0); split1(v.y, h1, l1);
    split1(v.z, h2, l2); split1(v.w, h3, l3);
    reinterpret_cast<bf162*>(H)[2 * j]     = bf162(h0, h1);
    reinterpret_cast<bf162*>(H)[2 * j + 1] = bf162(h2, h3);
    reinterpret_cast<bf162*>(L)[2 * j]     = bf162(l0, l1);
    reinterpret_cast<bf162*>(L)[2 * j + 1] = bf162(l2, l3);
}

// ---------------------------------------------------------------------------
// V transpose + split: VtH/VtL[b][c][t] = split(V[b][t][c])
// ---------------------------------------------------------------------------
__global__ void __launch_bounds__(256)
transpose_split(const float* __restrict__ V, bf16* __restrict__ TH,
                bf16* __restrict__ TL)
{
    __shared__ float t[32][33];
    const int b = blockIdx.z;
    const int c0 = blockIdx.x * 32, t0 = blockIdx.y * 32;
    const float* Vb = V + (size_t)b * TDIM * CDIM;
    bf16* THb = TH + (size_t)b * TDIM * CDIM;
    bf16* TLb = TL + (size_t)b * TDIM * CDIM;
    const int tx = threadIdx.x, ty = threadIdx.y;
    #pragma unroll
    for (int i = 0; i < 32; i += 8)
        t[ty + i][tx] = Vb[(size_t)(t0 + ty + i) * CDIM + c0 + tx];
    __syncthreads();
    #pragma unroll
    for (int i = 0; i < 32; i += 8) {
        bf16 h, l;
        split1(t[tx][ty + i], h, l);
        const size_t idx = (size_t)(c0 + ty + i) * TDIM + t0 + tx;
        THb[idx] = h;
        TLb[idx] = l;
    }
}

// ---------------------------------------------------------------------------
extern "C" void kernel_launch(void* const* d_in, const int* in_sizes, int n_in,
                              void* d_out, int out_size)
{
    const float* x  = (const float*)d_in[0];
    const float* Wq = (const float*)d_in[1];
    const float* bq = (const float*)d_in[2];
    const float* Wk = (const float*)d_in[3];
    const float* bk = (const float*)d_in[4];
    const float* Wv = (const float*)d_in[5];
    const float* bv = (const float*)d_in[6];
    const float* Wo = (const float*)d_in[7];
    const float* bo = (const float*)d_in[8];
    float* out = (float*)d_out;

    bf16 *xh, *xl, *wqh, *wql, *wkh, *wkl, *wvh, *wvl, *woh, *wol;
    bf16 *qh, *ql, *kh, *kl, *vth, *vtl, *ph, *pl, *yh, *yl;
    float *v, *rs;
    cudaGetSymbolAddress((void**)&xh, g_xh);   cudaGetSymbolAddress((void**)&xl, g_xl);
    cudaGetSymbolAddress((void**)&wqh, g_wqh); cudaGetSymbolAddress((void**)&wql, g_wql);
    cudaGetSymbolAddress((void**)&wkh, g_wkh); cudaGetSymbolAddress((void**)&wkl, g_wkl);
    cudaGetSymbolAddress((void**)&wvh, g_wvh); cudaGetSymbolAddress((void**)&wvl, g_wvl);
    cudaGetSymbolAddress((void**)&woh, g_woh); cudaGetSymbolAddress((void**)&wol, g_wol);
    cudaGetSymbolAddress((void**)&qh, g_qh);   cudaGetSymbolAddress((void**)&ql, g_ql);
    cudaGetSymbolAddress((void**)&kh, g_kh);   cudaGetSymbolAddress((void**)&kl, g_kl);
    cudaGetSymbolAddress((void**)&v, g_v);
    cudaGetSymbolAddress((void**)&vth, g_vth); cudaGetSymbolAddress((void**)&vtl, g_vtl);
    cudaGetSymbolAddress((void**)&ph, g_ph);   cudaGetSymbolAddress((void**)&pl, g_pl);
    cudaGetSymbolAddress((void**)&rs, g_rsum);
    cudaGetSymbolAddress((void**)&yh, g_yh);   cudaGetSymbolAddress((void**)&yl, g_yl);

    cudaFuncSetAttribute(qkv_pipe,            cudaFuncAttributeMaxDynamicSharedMemorySize, SMEM_SZ);
    cudaFuncSetAttribute(gemm_pipe<0, false>, cudaFuncAttributeMaxDynamicSharedMemorySize, SMEM_SZ);
    cudaFuncSetAttribute(gemm_pipe<1, false>, cudaFuncAttributeMaxDynamicSharedMemorySize, SMEM_SZ);
    cudaFuncSetAttribute(gemm_pipe<3, true >, cudaFuncAttributeMaxDynamicSharedMemorySize, SMEM_SZ);

    const dim3 blk(NTHREADS);
    const dim3 blk256(256);
    const float scale = 0.03125f;  // 1/sqrt(1024)
    const size_t sTC = (size_t)TDIM * CDIM;
    const size_t sTT = (size_t)TDIM * TDIM;

    // 1: rowsum zero, 2: one-shot splits
    zero_rowsum<<<BDIM * TDIM / 256, blk256>>>(rs);
    const size_t nSplit = NTC / 4 + 4 * (NCC / 4);
    split_all<<<(int)(nSplit / 256), blk256>>>(x, Wq, Wk, Wv, Wo,
                                               xh, xl, wqh, wql, wkh, wkl,
                                               wvh, wvl, woh, wol);

    // 3: merged Q/K/V projections (z selects operand set)
    const dim3 gqkv(CDIM / 128, (BDIM * TDIM) / 128, 3);     // (8, 64, 3)
    qkv_pipe<<<gqkv, blk, SMEM_SZ>>>(xh, xl,
                                     wqh, wql, bq, qh, ql,
                                     wkh, wkl, bk, kh, kl,
                                     wvh, wvl, bv, v);

    // 4: scores fused with exp + mask + row-sum
    const dim3 gs(TDIM / 128, TDIM / 128, BDIM);             // (16, 16, 4)
    gemm_pipe<1, false><<<gs, blk, SMEM_SZ>>>(qh, ql, kh, kl, nullptr, rs,
                                              nullptr, ph, pl, TDIM, CDIM,
                                              sTC, sTC, sTT, scale);

    // 5: V transpose + split -> [b][c][t] hi/lo
    transpose_split<<<dim3(CDIM / 32, TDIM / 32, BDIM), dim3(32, 8)>>>(v, vth, vtl);

    // 6: y = (P @ Vt.T) / rowsum  (band K-skip)
    const dim3 ga(CDIM / 128, TDIM / 128, BDIM);             // (8, 16, 4)
    gemm_pipe<3, true><<<ga, blk, SMEM_SZ>>>(ph, pl, vth, vtl, nullptr, rs,
                                             nullptr, yh, yl, CDIM, TDIM,
                                             sTT, sTC, sTC, 0.f);

    // 7: out = y @ Wo.T + bo (fp32)
    const dim3 go(CDIM / 128, (BDIM * TDIM) / 128, 1);       // (8, 64, 1)
    gemm_pipe<0, false><<<go, blk, SMEM_SZ>>>(yh, yl, woh, wol, bo, nullptr,
                                              out, nullptr, nullptr, CDIM, CDIM,
                                              0, 0, 0, 0.f);
}

// round 16
// speedup vs baseline: 1.4849x; 1.4849x over previous
#include <cuda_runtime.h>
#include <cuda_fp16.h>
#include <cstdint>

#define BDIM 4
#define TDIM 2048
#define CDIM 1024
#define WIN  16

typedef __half  f16;
typedef __half2 f162;

// ---------------- scratch (allocation-free rule: __device__ globals) --------
#define NTC ((size_t)BDIM * TDIM * CDIM)
#define NTT ((size_t)BDIM * TDIM * TDIM)
#define NCC ((size_t)CDIM * CDIM)
__device__ f16   g_xh[NTC],  g_xl[NTC];           // x: fp16 hi/lo pair (A-side)
__device__ f16   g_wqh[NCC], g_wkh[NCC], g_wvh[NCC], g_woh[NCC];  // W: hi only
__device__ f16   g_qh[NTC],  g_ql[NTC];           // Q: pair (A in scores)
__device__ f16   g_kh[NTC],  g_kl[NTC];           // K: pair stored, hi used as B
__device__ float g_v[NTC];
__device__ f16   g_vth[NTC];                      // V^T: hi only (B in AV)
__device__ f16   g_ph[NTT],  g_pl[NTT];           // P = exp scores: pair (A in AV)
__device__ float g_rsum[(size_t)BDIM * TDIM];     // row sums of exp
__device__ f16   g_yh[NTC],  g_yl[NTC];           // y: pair (A in O-proj)

// ---------------- low-level helpers (sm_80-portable PTX only) ---------------
__device__ __forceinline__ uint32_t smem_u32(const void* p) {
    uint32_t a;
    asm("{ .reg .u64 t; cvta.to.shared.u64 t, %1; cvt.u32.u64 %0, t; }"
        : "=r"(a) : "l"(p));
    return a;
}
__device__ __forceinline__ uint32_t swz(uint32_t off) {      // SW128 swizzle
    return off ^ ((off >> 3) & 0x70);
}
__device__ __forceinline__ void cp16(uint32_t dst, const void* src) {
    asm volatile("cp.async.cg.shared.global [%0], [%1], 16;"
                 :: "r"(dst), "l"(src));
}
__device__ __forceinline__ void cp_commit() {
    asm volatile("cp.async.commit_group;" ::: "memory");
}
__device__ __forceinline__ void cp_wait2() {
    asm volatile("cp.async.wait_group 2;" ::: "memory");
}
__device__ __forceinline__ void ldsm4(uint32_t (&r)[4], uint32_t addr) {
    asm volatile("ldmatrix.sync.aligned.m8n8.x4.shared.b16 {%0,%1,%2,%3}, [%4];"
                 : "=r"(r[0]), "=r"(r[1]), "=r"(r[2]), "=r"(r[3]) : "r"(addr));
}
__device__ __forceinline__ void mma16816(float (&c)[4], const uint32_t (&a)[4],
                                         const uint32_t (&b)[2]) {
    asm volatile(
        "mma.sync.aligned.m16n8k16.row.col.f32.f16.f16.f32 "
        "{%0,%1,%2,%3}, {%4,%5,%6,%7}, {%8,%9}, {%0,%1,%2,%3};"
        : "+f"(c[0]), "+f"(c[1]), "+f"(c[2]), "+f"(c[3])
        : "r"(a[0]), "r"(a[1]), "r"(a[2]), "r"(a[3]), "r"(b[0]), "r"(b[1]));
}
__device__ __forceinline__ void split1(float v, f16& h, f16& l) {
    h = __float2half_rn(v);
    l = __float2half_rn(v - __half2float(h));
}
__device__ __forceinline__ void split_store2(f16* H, f16* L, size_t idx,
                                             float v0, float v1) {
    f16 h0, l0, h1, l1;
    split1(v0, h0, l0);
    split1(v1, h1, l1);
    *reinterpret_cast<f162*>(&H[idx]) = __halves2half2(h0, h1);
    *reinterpret_cast<f162*>(&L[idx]) = __halves2half2(l0, l1);
}

// ===========================================================================
// Pipelined 128x128 mainloop: BK=64, 16 warps (4x4), warp tile 32x32,
// 512 threads, 3-stage cp.async, double-buffered ldmatrix fragments.
// fp16 asymmetric 2-pass: C = Ah*Bh + Al*Bh  (A split to 22 bits, B hi-only;
// dropped A*Bl term ~2^-12 relative).
// Stage layout: [Ah 16K][Al 16K][Bh 16K] = 48K/stage.
// ===========================================================================
#define NTHREADS    512
#define STAGE_BYTES 49152
#define NSTAGE      3
#define SMEM_SZ     (NSTAGE * STAGE_BYTES)

struct Frag {
    uint32_t ah[2][4], al[2][4];
    uint32_t bh[4][2];
};

__device__ __forceinline__ void frag_load(Frag& f, uint32_t tAh, uint32_t tAl,
                                          uint32_t tBh,
                                          uint32_t aoff, uint32_t boff, int kk)
{
    const uint32_t ka = (uint32_t)kk * 32;           // 16 f16 = 32 bytes
    #pragma unroll
    for (int mi = 0; mi < 2; mi++) {
        const uint32_t off = aoff + mi * 2048 + ka;
        ldsm4(f.ah[mi], tAh + swz(off));
        ldsm4(f.al[mi], tAl + swz(off));
    }
    #pragma unroll
    for (int p = 0; p < 2; p++) {                    // each ldsm4 covers 2 n-tiles
        const uint32_t off = boff + (uint32_t)(p * 16 * 128) + ka;
        uint32_t t4[4];
        ldsm4(t4, tBh + swz(off));
        f.bh[p * 2][0] = t4[0]; f.bh[p * 2][1] = t4[1];
        f.bh[p * 2 + 1][0] = t4[2]; f.bh[p * 2 + 1][1] = t4[3];
    }
}

__device__ __forceinline__ void frag_mma(float acc[2][4][4], const Frag& f)
{
    #pragma unroll
    for (int mi = 0; mi < 2; mi++)
        #pragma unroll
        for (int ni = 0; ni < 4; ni++)
            mma16816(acc[mi][ni], f.ah[mi], f.bh[ni]);
    #pragma unroll
    for (int mi = 0; mi < 2; mi++)
        #pragma unroll
        for (int ni = 0; ni < 4; ni++)
            mma16816(acc[mi][ni], f.al[mi], f.bh[ni]);
}

__device__ __forceinline__ void mainloop128(
    const f16* __restrict__ Ah, const f16* __restrict__ Al,
    const f16* __restrict__ Bh,
    int K_, int kstart, int m0, int n0, int tid,
    uint32_t sbase, float acc[2][4][4])
{
    auto load_stage = [&](int stg, int k0) {
        const uint32_t sb = sbase + stg * STAGE_BYTES;
        #pragma unroll
        for (int i = 0; i < 2; i++) {
            const int id = tid + i * NTHREADS;       // 1024 16B-chunks per tile
            const int row = id >> 3, kc = id & 7;
            const uint32_t d = swz((uint32_t)(row * 128 + kc * 16));
            const size_t ga = (size_t)(m0 + row) * K_ + k0 + kc * 8;
            const size_t gb = (size_t)(n0 + row) * K_ + k0 + kc * 8;
            cp16(sb +         d, Ah + ga);
            cp16(sb + 16384 + d, Al + ga);
            cp16(sb + 32768 + d, Bh + gb);
        }
    };

    const int wid = tid >> 5, lane = tid & 31;
    const int warpM = wid & 3, warpN = wid >> 2;     // 4x4 warp grid
    const uint32_t aoff = (uint32_t)((warpM * 32 + (lane & 15)) * 128 + (lane >> 4) * 16);
    const int bgrp = lane >> 3, bl8 = lane & 7;
    const uint32_t boff = (uint32_t)((warpN * 32 + (bgrp >> 1) * 8 + bl8) * 128 + (bgrp & 1) * 16);

    load_stage(0, kstart);
    cp_commit();
    if (kstart + 64 < K_) load_stage(1, kstart + 64);
    cp_commit();

    Frag f0, f1;
    int stg = 0;
    for (int k0 = kstart; k0 < K_; k0 += 64) {
        const int kpre = k0 + 128;
        if (kpre < K_) {
            int sl = stg + 2;
            if (sl >= NSTAGE) sl -= NSTAGE;
            load_stage(sl, kpre);
        }
        cp_commit();
        cp_wait2();
        __syncthreads();

        const uint32_t tb  = sbase + stg * STAGE_BYTES;
        const uint32_t tAh = tb, tAl = tb + 16384, tBh = tb + 32768;

        frag_load(f0, tAh, tAl, tBh, aoff, boff, 0);
        frag_load(f1, tAh, tAl, tBh, aoff, boff, 1);
        frag_mma(acc, f0);
        frag_load(f0, tAh, tAl, tBh, aoff, boff, 2);
        frag_mma(acc, f1);
        frag_load(f1, tAh, tAl, tBh, aoff, boff, 3);
        frag_mma(acc, f0);
        frag_mma(acc, f1);

        __syncthreads();
        if (++stg == NSTAGE) stg = 0;
    }
}

// ===========================================================================
// Merged Q/K/V projections: z=0 -> Q (pair), z=1 -> K (pair), z=2 -> V fp32.
// ===========================================================================
__global__ void __launch_bounds__(NTHREADS)
qkv_pipe(const f16* __restrict__ Ah, const f16* __restrict__ Al,
         const f16* __restrict__ BhQ, const float* __restrict__ bQ,
         f16* __restrict__ ChQ, f16* __restrict__ ClQ,
         const f16* __restrict__ BhK, const float* __restrict__ bK,
         f16* __restrict__ ChK, f16* __restrict__ ClK,
         const f16* __restrict__ BhV, const float* __restrict__ bV,
         float* __restrict__ CfV)
{
    extern __shared__ __align__(1024) char smem[];
    const int z = blockIdx.z;
    const f16* Bh;
    const float* bias;
    f16 *Ch = nullptr, *Cl = nullptr;
    float* Cf = nullptr;
    if (z == 0)      { Bh = BhQ; bias = bQ; Ch = ChQ; Cl = ClQ; }
    else if (z == 1) { Bh = BhK; bias = bK; Ch = ChK; Cl = ClK; }
    else             { Bh = BhV; bias = bV; Cf = CfV; }

    const int m0 = blockIdx.y * 128;
    const int n0 = blockIdx.x * 128;
    const int tid = threadIdx.x;

    float acc[2][4][4];
    #pragma unroll
    for (int i = 0; i < 2; i++)
        #pragma unroll
        for (int j = 0; j < 4; j++)
            #pragma unroll
            for (int t = 0; t < 4; t++) acc[i][j][t] = 0.0f;

    mainloop128(Ah, Al, Bh, CDIM, 0, m0, n0, tid, smem_u32(smem), acc);

    const int wid = tid >> 5, lane = tid & 31;
    const int warpM = wid & 3, warpN = wid >> 2;
    const int rbase = m0 + warpM * 32 + (lane >> 2);
    const int cbase = n0 + warpN * 32 + (lane & 3) * 2;
    #pragma unroll
    for (int mi = 0; mi < 2; mi++) {
        const int ra = rbase + mi * 16, rb = ra + 8;
        #pragma unroll
        for (int ni = 0; ni < 4; ni++) {
            const int c = cbase + ni * 8;
            const float b0 = bias[c], b1 = bias[c + 1];
            const float v0 = acc[mi][ni][0] + b0, v1 = acc[mi][ni][1] + b1;
            const float v2 = acc[mi][ni][2] + b0, v3 = acc[mi][ni][3] + b1;
            if (Cf) {
                *reinterpret_cast<float2*>(&Cf[(size_t)ra * CDIM + c]) = make_float2(v0, v1);
                *reinterpret_cast<float2*>(&Cf[(size_t)rb * CDIM + c]) = make_float2(v2, v3);
            } else {
                split_store2(Ch, Cl, (size_t)ra * CDIM + c, v0, v1);
                split_store2(Ch, Cl, (size_t)rb * CDIM + c, v2, v3);
            }
        }
    }
}

// ===========================================================================
// gemm_pipe<EPI, AVSKIP>: EPI 0 fp32+bias (O proj); EPI 1 scores (exp+mask+
// rowsum atomics, masked tiles exit without writing); EPI 3 AV (normalize).
// AVSKIP: start K at m0-64 (P exactly 0 below the band).
// ===========================================================================
template <int EPI, bool AVSKIP>
__global__ void __launch_bounds__(NTHREADS)
gemm_pipe(const f16* __restrict__ Ah, const f16* __restrict__ Al,
          const f16* __restrict__ Bh,
          const float* __restrict__ bias, float* __restrict__ rowsum,
          float* __restrict__ Cf, f16* __restrict__ Ch, f16* __restrict__ Cl,
          int N_, int K_, size_t sA, size_t sB, size_t sC, float scale)
{
    extern __shared__ __align__(1024) char smem[];
    const int bz = blockIdx.z;
    Ah += (size_t)bz * sA;  Al += (size_t)bz * sA;
    Bh += (size_t)bz * sB;
    const size_t cOff = (size_t)bz * sC;

    const int m0 = blockIdx.y * 128;
    const int n0 = blockIdx.x * 128;
    const int tid = threadIdx.x;

    if (EPI == 1) {
        if (n0 + 127 < m0 - WIN) return;     // fully masked tile
    }

    int kstart = 0;
    if (AVSKIP) kstart = (m0 >= 64) ? m0 - 64 : 0;

    float acc[2][4][4];
    #pragma unroll
    for (int i = 0; i < 2; i++)
        #pragma unroll
        for (int j = 0; j < 4; j++)
            #pragma unroll
            for (int t = 0; t < 4; t++) acc[i][j][t] = 0.0f;

    mainloop128(Ah, Al, Bh, K_, kstart, m0, n0, tid, smem_u32(smem), acc);

    const int wid = tid >> 5, lane = tid & 31;
    const int warpM = wid & 3, warpN = wid >> 2;
    const int rbase = m0 + warpM * 32 + (lane >> 2);
    const int cbase = n0 + warpN * 32 + (lane & 3) * 2;
    #pragma unroll
    for (int mi = 0; mi < 2; mi++) {
        const int ra = rbase + mi * 16, rb = ra + 8;
        float sum_a = 0.f, sum_b = 0.f;
        float ia = 0.f, ib = 0.f;
        if (EPI == 3) {
            ia = 1.0f / __ldg(&rowsum[bz * TDIM + ra]);
            ib = 1.0f / __ldg(&rowsum[bz * TDIM + rb]);
        }
        #pragma unroll
        for (int ni = 0; ni < 4; ni++) {
            const int c = cbase + ni * 8;
            const float v0 = acc[mi][ni][0], v1 = acc[mi][ni][1];
            const float v2 = acc[mi][ni][2], v3 = acc[mi][ni][3];
            if (EPI == 0) {
                const float b0 = bias[c], b1 = bias[c + 1];
                *reinterpret_cast<float2*>(&Cf[cOff + (size_t)ra * N_ + c]) =
                    make_float2(v0 + b0, v1 + b1);
                *reinterpret_cast<float2*>(&Cf[cOff + (size_t)rb * N_ + c]) =
                    make_float2(v2 + b0, v3 + b1);
            } else if (EPI == 1) {
                const float p0 = (c     >= ra - WIN) ? __expf(v0 * scale) : 0.f;
                const float p1 = (c + 1 >= ra - WIN) ? __expf(v1 * scale) : 0.f;
                const float p2 = (c     >= rb - WIN) ? __expf(v2 * scale) : 0.f;
                const float p3 = (c + 1 >= rb - WIN) ? __expf(v3 * scale) : 0.f;
                split_store2(Ch, Cl, cOff + (size_t)ra * N_ + c, p0, p1);
                split_store2(Ch, Cl, cOff + (size_t)rb * N_ + c, p2, p3);
                sum_a += p0 + p1;
                sum_b += p2 + p3;
            } else {  // EPI == 3
                split_store2(Ch, Cl, cOff + (size_t)ra * N_ + c, v0 * ia, v1 * ia);
                split_store2(Ch, Cl, cOff + (size_t)rb * N_ + c, v2 * ib, v3 * ib);
            }
        }
        if (EPI == 1) {
            sum_a += __shfl_xor_sync(0xffffffffu, sum_a, 1);
            sum_a += __shfl_xor_sync(0xffffffffu, sum_a, 2);
            sum_b += __shfl_xor_sync(0xffffffffu, sum_b, 1);
            sum_b += __shfl_xor_sync(0xffffffffu, sum_b, 2);
            if ((lane & 3) == 0) {
                atomicAdd(&rowsum[bz * TDIM + ra], sum_a);
                atomicAdd(&rowsum[bz * TDIM + rb], sum_b);
            }
        }
    }
}

// ---------------------------------------------------------------------------
__global__ void __launch_bounds__(256)
zero_rowsum(float* __restrict__ r)
{
    r[blockIdx.x * 256 + threadIdx.x] = 0.0f;
}

// ---------------------------------------------------------------------------
// One-shot split: x -> fp16 hi/lo pair; four weights -> fp16 hi only.
// ---------------------------------------------------------------------------
__global__ void __launch_bounds__(256)
split_all(const float* __restrict__ x,  const float* __restrict__ Wq,
          const float* __restrict__ Wk, const float* __restrict__ Wv,
          const float* __restrict__ Wo,
          f16* __restrict__ xh,  f16* __restrict__ xl,
          f16* __restrict__ qh,  f16* __restrict__ kh,
          f16* __restrict__ vh,  f16* __restrict__ oh)
{
    const size_t nX = NTC / 4, nW = NCC / 4;
    size_t i = (size_t)blockIdx.x * 256 + threadIdx.x;
    if (i < nX) {
        const float4 v = reinterpret_cast<const float4*>(x)[i];
        f16 h0, l0, h1, l1, h2, l2, h3, l3;
        split1(v.x, h0, l0); split1(v.y, h1, l1);
        split1(v.z, h2, l2); split1(v.w, h3, l3);
        reinterpret_cast<f162*>(xh)[2 * i]     = __halves2half2(h0, h1);
        reinterpret_cast<f162*>(xh)[2 * i + 1] = __halves2half2(h2, h3);
        reinterpret_cast<f162*>(xl)[2 * i]     = __halves2half2(l0, l1);
        reinterpret_cast<f162*>(xl)[2 * i + 1] = __halves2half2(l2, l3);
        return;
    }
    const float* src;
    f16* H;
    size_t j;
    if (i < nX + nW)          { src = Wq; H = qh; j = i - nX; }
    else if (i < nX + 2 * nW) { src = Wk; H = kh; j = i - nX - nW; }
    else if (i < nX + 3 * nW) { src = Wv; H = vh; j = i - nX - 2 * nW; }
    else                      { src = Wo; H = oh; j = i - nX - 3 * nW; }
    const float4 v = reinterpret_cast<const float4*>(src)[j];
    reinterpret_cast<f162*>(H)[2 * j] =
        __halves2half2(__float2half_rn(v.x), __float2half_rn(v.y));
    reinterpret_cast<f162*>(H)[2 * j + 1] =
        __halves2half2(__float2half_rn(v.z), __float2half_rn(v.w));
}

// ---------------------------------------------------------------------------
// V transpose: Vt_hi[b][c][t] = fp16(V[b][t][c])  (B-side: hi only)
// ---------------------------------------------------------------------------
__global__ void __launch_bounds__(256)
transpose_split(const float* __restrict__ V, f16* __restrict__ TH)
{
    __shared__ float t[32][33];
    const int b = blockIdx.z;
    const int c0 = blockIdx.x * 32, t0 = blockIdx.y * 32;
    const float* Vb = V + (size_t)b * TDIM * CDIM;
    f16* THb = TH + (size_t)b * TDIM * CDIM;
    const int tx = threadIdx.x, ty = threadIdx.y;
    #pragma unroll
    for (int i = 0; i < 32; i += 8)
        t[ty + i][tx] = Vb[(size_t)(t0 + ty + i) * CDIM + c0 + tx];
    __syncthreads();
    #pragma unroll
    for (int i = 0; i < 32; i += 8)
        THb[(size_t)(c0 + ty + i) * TDIM + t0 + tx] = __float2half_rn(t[tx][ty + i]);
}

// ---------------------------------------------------------------------------
extern "C" void kernel_launch(void* const* d_in, const int* in_sizes, int n_in,
                              void* d_out, int out_size)
{
    const float* x  = (const float*)d_in[0];
    const float* Wq = (const float*)d_in[1];
    const float* bq = (const float*)d_in[2];
    const float* Wk = (const float*)d_in[3];
    const float* bk = (const float*)d_in[4];
    const float* Wv = (const float*)d_in[5];
    const float* bv = (const float*)d_in[6];
    const float* Wo = (const float*)d_in[7];
    const float* bo = (const float*)d_in[8];
    float* out = (float*)d_out;

    f16 *xh, *xl, *wqh, *wkh, *wvh, *woh;
    f16 *qh, *ql, *kh, *kl, *vth, *ph, *pl, *yh, *yl;
    float *v, *rs;
    cudaGetSymbolAddress((void**)&xh, g_xh);   cudaGetSymbolAddress((void**)&xl, g_xl);
    cudaGetSymbolAddress((void**)&wqh, g_wqh); cudaGetSymbolAddress((void**)&wkh, g_wkh);
    cudaGetSymbolAddress((void**)&wvh, g_wvh); cudaGetSymbolAddress((void**)&woh, g_woh);
    cudaGetSymbolAddress((void**)&qh, g_qh);   cudaGetSymbolAddress((void**)&ql, g_ql);
    cudaGetSymbolAddress((void**)&kh, g_kh);   cudaGetSymbolAddress((void**)&kl, g_kl);
    cudaGetSymbolAddress((void**)&v, g_v);
    cudaGetSymbolAddress((void**)&vth, g_vth);
    cudaGetSymbolAddress((void**)&ph, g_ph);   cudaGetSymbolAddress((void**)&pl, g_pl);
    cudaGetSymbolAddress((void**)&rs, g_rsum);
    cudaGetSymbolAddress((void**)&yh, g_yh);   cudaGetSymbolAddress((void**)&yl, g_yl);

    cudaFuncSetAttribute(qkv_pipe,            cudaFuncAttributeMaxDynamicSharedMemorySize, SMEM_SZ);
    cudaFuncSetAttribute(gemm_pipe<0, false>, cudaFuncAttributeMaxDynamicSharedMemorySize, SMEM_SZ);
    cudaFuncSetAttribute(gemm_pipe<1, false>, cudaFuncAttributeMaxDynamicSharedMemorySize, SMEM_SZ);
    cudaFuncSetAttribute(gemm_pipe<3, true >, cudaFuncAttributeMaxDynamicSharedMemorySize, SMEM_SZ);

    const dim3 blk(NTHREADS);
    const dim3 blk256(256);
    const float scale = 0.03125f;  // 1/sqrt(1024)
    const size_t sTC = (size_t)TDIM * CDIM;
    const size_t sTT = (size_t)TDIM * TDIM;

    // 1: rowsum zero, 2: one-shot splits
    zero_rowsum<<<BDIM * TDIM / 256, blk256>>>(rs);
    const size_t nSplit = NTC / 4 + 4 * (NCC / 4);
    split_all<<<(int)(nSplit / 256), blk256>>>(x, Wq, Wk, Wv, Wo,
                                               xh, xl, wqh, wkh, wvh, woh);

    // 3: merged Q/K/V projections (z selects operand set)
    const dim3 gqkv(CDIM / 128, (BDIM * TDIM) / 128, 3);     // (8, 64, 3)
    qkv_pipe<<<gqkv, blk, SMEM_SZ>>>(xh, xl,
                                     wqh, bq, qh, ql,
                                     wkh, bk, kh, kl,
                                     wvh, bv, v);

    // 4: scores fused with exp + mask + row-sum  (B = K hi)
    const dim3 gs(TDIM / 128, TDIM / 128, BDIM);             // (16, 16, 4)
    gemm_pipe<1, false><<<gs, blk, SMEM_SZ>>>(qh, ql, kh, nullptr, rs,
                                              nullptr, ph, pl, TDIM, CDIM,
                                              sTC, sTC, sTT, scale);

    // 5: V transpose -> [b][c][t] fp16 hi
    transpose_split<<<dim3(CDIM / 32, TDIM / 32, BDIM), dim3(32, 8)>>>(v, vth);

    // 6: y = (P @ Vt.T) / rowsum  (band K-skip)
    const dim3 ga(CDIM / 128, TDIM / 128, BDIM);             // (8, 16, 4)
    gemm_pipe<3, true><<<ga, blk, SMEM_SZ>>>(ph, pl, vth, nullptr, rs,
                                             nullptr, yh, yl, CDIM, TDIM,
                                             sTT, sTC, sTC, 0.f);

    // 7: out = y @ Wo.T + bo (fp32)
    const dim3 go(CDIM / 128, (BDIM * TDIM) / 128, 1);       // (8, 64, 1)
    gemm_pipe<0, false><<<go, blk, SMEM_SZ>>>(yh, yl, woh, bo, nullptr,
                                              out, nullptr, nullptr, CDIM, CDIM,
                                              0, 0, 0, 0.f);
}